// round 6
// baseline (speedup 1.0000x reference)
#include <cuda_runtime.h>

// ---------------------------------------------------------------------------
// CML2DWithStats, round 5: round-3 scalar skeleton + deferred drive add.
//
//   g_{t+1} = clamp( conv3x3( m_t, K' ) + BETA*drive ),  m = g*(1-g)
//   K' = R*(1-BETA)*(EPS*K + (1-EPS)*delta_center)
//
// One CTA per (batch, channel, 64-row strip). SMEM = two 96x256 mapped
// buffers (split-quad layout: row*256 + [tx*4 | 128 + tx*4], conflict-free).
// Each thread owns 3 row-pairs (p = ty + 16k); a pair loads 4 input rows for
// 2 outputs (4 LDS.128 + 4 SHFL per row).
//
// Deferred drive: raw drive is loaded at pair START (LDG.128 x4, L2-resident)
// but only consumed at pair END (g = clamp(fma(beta, d, conv))), so the
// ~240-cycle L2 latency hides behind the 144-FMA conv.
// ---------------------------------------------------------------------------

#define R_PARAM  3.9f
#define EPS_P    0.3f
#define BETA_P   0.15f
#define NSTEPS   15
#define CLAMP_LO 1e-4f
#define CLAMP_HI (1.0f - 1e-4f)

constexpr int W      = 256;
constexpr int HIMG   = 256;
constexpr int STRIP  = 64;
constexpr int HALO   = 16;
constexpr int BROWS  = 96;
constexpr int TXN    = 32;
constexpr int TYN    = 16;
constexpr int NTHR   = TXN * TYN;          // 512
constexpr int NPLANE = W * HIMG;
constexpr long long NTOT = 16LL * 8 * NPLANE;

__device__ __forceinline__ float clampg(float v) {
    return fminf(fmaxf(v, CLAMP_LO), CLAMP_HI);
}

__global__ __launch_bounds__(NTHR, 1)
void cml_fused_kernel(const float* __restrict__ drive,
                      const float* __restrict__ Klocal,
                      float* __restrict__ out)
{
    extern __shared__ float sm[];
    float* MB0 = sm;
    float* MB1 = sm + BROWS * W;

    const int tx = threadIdx.x;
    const int ty = threadIdx.y;
    const int strip = blockIdx.x;
    const int c     = blockIdx.y;
    const int b     = blockIdx.z;
    const int row0  = strip * STRIP - HALO;
    const int x4    = tx * 4;
    const int x0    = tx * 8;

    // Folded kernel K' = R*(1-BETA)*(EPS*K + (1-EPS)*delta)
    float kk[3][3];
    {
        const float* kc = Klocal + c * 9;
        #pragma unroll
        for (int j = 0; j < 3; ++j)
            #pragma unroll
            for (int i = 0; i < 3; ++i) {
                float v = EPS_P * kc[j * 3 + i];
                if (j == 1 && i == 1) v += (1.0f - EPS_P);
                kk[j][i] = R_PARAM * (1.0f - BETA_P) * v;
            }
    }

    const long long plane = (long long)(b * 8 + c) * NPLANE;
    const float* dpl = drive + plane;

    // static per-thread pair geometry (independent of step)
    // pair k: p = ty + 16k, rows r0 = 2p, r0+1 ; image rows ir0, ir0+1
    int  r0a[3], ir0a[3];
    bool inimg[3];
    #pragma unroll
    for (int k = 0; k < 3; ++k) {
        int p  = ty + 16 * k;
        r0a[k]  = 2 * p;
        ir0a[k] = row0 + 2 * p;
        inimg[k] = (unsigned)ir0a[k] < (unsigned)HIMG;
    }

    // ---- init: MB0 <- mapped(drive) on in-image rows, 0 elsewhere; MB1 <- 0 ----
    #pragma unroll
    for (int k = 0; k < 6; ++k) {
        int r  = ty + TYN * k;
        int ir = row0 + r;
        float* p0 = MB0 + r * W;
        float* p1 = MB1 + r * W;
        float4 z = make_float4(0.f, 0.f, 0.f, 0.f);
        *reinterpret_cast<float4*>(p1 + x4)       = z;
        *reinterpret_cast<float4*>(p1 + 128 + x4) = z;
        if ((unsigned)ir < (unsigned)HIMG) {
            const float* dr = dpl + (long long)ir * W + x0;
            float4 dA = *reinterpret_cast<const float4*>(dr);
            float4 dB = *reinterpret_cast<const float4*>(dr + 4);
            float4 mA, mB;
            mA.x = fmaf(-dA.x, dA.x, dA.x);  mA.y = fmaf(-dA.y, dA.y, dA.y);
            mA.z = fmaf(-dA.z, dA.z, dA.z);  mA.w = fmaf(-dA.w, dA.w, dA.w);
            mB.x = fmaf(-dB.x, dB.x, dB.x);  mB.y = fmaf(-dB.y, dB.y, dB.y);
            mB.z = fmaf(-dB.z, dB.z, dB.z);  mB.w = fmaf(-dB.w, dB.w, dB.w);
            *reinterpret_cast<float4*>(p0 + x4)       = mA;
            *reinterpret_cast<float4*>(p0 + 128 + x4) = mB;
        } else {
            *reinterpret_cast<float4*>(p0 + x4)       = z;
            *reinterpret_cast<float4*>(p0 + 128 + x4) = z;
        }
    }
    __syncthreads();

    // stats: 2 interior pair-slots per thread. [rowInPair*8 + i]
    float sum0[16], ssq0[16], sum1[16], ssq1[16];
    #pragma unroll
    for (int i = 0; i < 16; ++i) {
        sum0[i] = 0.f; ssq0[i] = 0.f; sum1[i] = 0.f; ssq1[i] = 0.f;
    }

    // accumulate one loaded row (m0..m7,lm,rm live) into acc with kernel row cc
    #define ACCROW(acc, cc)                                                    \
        {                                                                      \
            float c0 = (cc)[0], c1 = (cc)[1], c2 = (cc)[2];                    \
            acc[0] = fmaf(c0, lm, fmaf(c1, m0, fmaf(c2, m1, acc[0])));         \
            acc[1] = fmaf(c0, m0, fmaf(c1, m1, fmaf(c2, m2, acc[1])));         \
            acc[2] = fmaf(c0, m1, fmaf(c1, m2, fmaf(c2, m3, acc[2])));         \
            acc[3] = fmaf(c0, m2, fmaf(c1, m3, fmaf(c2, m4, acc[3])));         \
            acc[4] = fmaf(c0, m3, fmaf(c1, m4, fmaf(c2, m5, acc[4])));         \
            acc[5] = fmaf(c0, m4, fmaf(c1, m5, fmaf(c2, m6, acc[5])));         \
            acc[6] = fmaf(c0, m5, fmaf(c1, m6, fmaf(c2, m7, acc[6])));         \
            acc[7] = fmaf(c0, m6, fmaf(c1, m7, fmaf(c2, rm, acc[7])));         \
        }

    // conv for a pair of rows r0,r0+1: loads rows r0-1..r0+2 once each
    #define PAIR_CONV(Min, r0, acc0, acc1)                                     \
        {                                                                      \
            _Pragma("unroll")                                                  \
            for (int jr = 0; jr < 4; ++jr) {                                   \
                const float* rp = (Min) + ((r0) - 1 + jr) * W;                 \
                float4 qa = *reinterpret_cast<const float4*>(rp + x4);         \
                float4 qb = *reinterpret_cast<const float4*>(rp + 128 + x4);   \
                float m0 = qa.x, m1 = qa.y, m2 = qa.z, m3 = qa.w;              \
                float m4 = qb.x, m5 = qb.y, m6 = qb.z, m7 = qb.w;              \
                float lm = __shfl_up_sync(0xffffffffu, m7, 1);                 \
                float rm = __shfl_down_sync(0xffffffffu, m0, 1);               \
                if (tx == 0)  lm = 0.f;                                        \
                if (tx == 31) rm = 0.f;                                        \
                if (jr < 3) ACCROW(acc0, kk[jr])                               \
                if (jr > 0) ACCROW(acc1, kk[jr - 1])                           \
            }                                                                  \
        }

    // raw drive load (consumed only at pair end)
    #define LOAD_DRIVE_RAW(ir, dv)                                             \
        {                                                                      \
            const float* dr = dpl + (long long)(ir) * W + x0;                  \
            float4 dA = *reinterpret_cast<const float4*>(dr);                  \
            float4 dB = *reinterpret_cast<const float4*>(dr + 4);              \
            dv[0] = dA.x;  dv[1] = dA.y;  dv[2] = dA.z;  dv[3] = dA.w;         \
            dv[4] = dB.x;  dv[5] = dB.y;  dv[6] = dB.z;  dv[7] = dB.w;         \
        }

    #define STATS_ADD(sumA, ssqA, g0, g1)                                      \
        {                                                                      \
            _Pragma("unroll")                                                  \
            for (int i = 0; i < 8; ++i) {                                      \
                sumA[i]     += g0[i];  ssqA[i]     = fmaf(g0[i], g0[i], ssqA[i]); \
                sumA[i + 8] += g1[i];  ssqA[i + 8] = fmaf(g1[i], g1[i], ssqA[i + 8]); \
            }                                                                  \
        }

    // ---- steps 0..13 ----
    #pragma unroll 1
    for (int t = 0; t < NSTEPS - 1; ++t) {
        const float* Min  = (t & 1) ? MB1 : MB0;
        float*       Mout = (t & 1) ? MB0 : MB1;
        const int lo = 2 + t, hi = 93 - t;

        #pragma unroll
        for (int k = 0; k < 3; ++k) {
            const int r0 = r0a[k];
            if (r0 + 1 < lo || r0 > hi) continue;   // outside shrinking window
            if (!inimg[k]) continue;                // out of image (pair-aligned)
            const int ir0 = ir0a[k];

            float dv0[8], dv1[8];
            LOAD_DRIVE_RAW(ir0, dv0)
            LOAD_DRIVE_RAW(ir0 + 1, dv1)

            float acc0[8] = {0.f, 0.f, 0.f, 0.f, 0.f, 0.f, 0.f, 0.f};
            float acc1[8] = {0.f, 0.f, 0.f, 0.f, 0.f, 0.f, 0.f, 0.f};
            PAIR_CONV(Min, r0, acc0, acc1)

            float g0[8], g1[8], mm0[8], mm1[8];
            #pragma unroll
            for (int i = 0; i < 8; ++i) {
                g0[i]  = clampg(fmaf(BETA_P, dv0[i], acc0[i]));
                g1[i]  = clampg(fmaf(BETA_P, dv1[i], acc1[i]));
                mm0[i] = fmaf(-g0[i], g0[i], g0[i]);
                mm1[i] = fmaf(-g1[i], g1[i], g1[i]);
            }
            float* op0 = Mout + r0 * W;
            float* op1 = Mout + (r0 + 1) * W;
            *reinterpret_cast<float4*>(op0 + x4)       = make_float4(mm0[0], mm0[1], mm0[2], mm0[3]);
            *reinterpret_cast<float4*>(op0 + 128 + x4) = make_float4(mm0[4], mm0[5], mm0[6], mm0[7]);
            *reinterpret_cast<float4*>(op1 + x4)       = make_float4(mm1[0], mm1[1], mm1[2], mm1[3]);
            *reinterpret_cast<float4*>(op1 + 128 + x4) = make_float4(mm1[4], mm1[5], mm1[6], mm1[7]);

            // stats: interior pairs (rows 16..79). ty<8 -> k 1,2 ; ty>=8 -> k 0,1
            if (k == 0) {
                if (ty >= 8) STATS_ADD(sum0, ssq0, g0, g1)
            } else if (k == 1) {
                if (ty < 8) { STATS_ADD(sum0, ssq0, g0, g1) }
                else        { STATS_ADD(sum1, ssq1, g0, g1) }
            } else {
                if (ty < 8) STATS_ADD(sum1, ssq1, g0, g1)
            }
        }
        __syncthreads();
    }

    // ---- final step t=14: interior pairs only, write all 5 outputs ----
    {
        const float* Min = MB0;                 // t=14 even -> read MB0
        const float inv = 1.0f / (float)NSTEPS;

        #pragma unroll
        for (int k = 0; k < 3; ++k) {
            bool inter0 = (k == 0 && ty >= 8) || (k == 1 && ty < 8);
            bool inter1 = (k == 1 && ty >= 8) || (k == 2 && ty < 8);
            if (!inter0 && !inter1) continue;
            float* sumA = inter0 ? sum0 : sum1;
            float* ssqA = inter0 ? ssq0 : ssq1;

            const int r0  = r0a[k];
            const int ir0 = ir0a[k];

            float dv0[8], dv1[8];
            LOAD_DRIVE_RAW(ir0, dv0)
            LOAD_DRIVE_RAW(ir0 + 1, dv1)

            float acc0[8] = {0.f, 0.f, 0.f, 0.f, 0.f, 0.f, 0.f, 0.f};
            float acc1[8] = {0.f, 0.f, 0.f, 0.f, 0.f, 0.f, 0.f, 0.f};
            PAIR_CONV(Min, r0, acc0, acc1)

            #pragma unroll
            for (int half = 0; half < 2; ++half) {
                const float* acc = half ? acc1 : acc0;
                const float* dv  = half ? dv1  : dv0;
                const int off    = half * 8;
                long long idx = plane + (long long)(ir0 + half) * W + x0;

                float g[8], mean[8], var[8], del[8];
                #pragma unroll
                for (int i = 0; i < 8; ++i) {
                    g[i] = clampg(fmaf(BETA_P, dv[i], acc[i]));
                    float s  = sumA[off + i] + g[i];
                    float sq = fmaf(g[i], g[i], ssqA[off + i]);
                    mean[i] = s * inv;
                    var[i]  = fmaf(-mean[i], mean[i], sq * inv);
                    del[i]  = g[i] - dv[i];
                }
                *reinterpret_cast<float4*>(out + idx)                = make_float4(g[0], g[1], g[2], g[3]);
                *reinterpret_cast<float4*>(out + idx + 4)            = make_float4(g[4], g[5], g[6], g[7]);
                *reinterpret_cast<float4*>(out + NTOT + idx)         = make_float4(mean[0], mean[1], mean[2], mean[3]);
                *reinterpret_cast<float4*>(out + NTOT + idx + 4)     = make_float4(mean[4], mean[5], mean[6], mean[7]);
                *reinterpret_cast<float4*>(out + 2 * NTOT + idx)     = make_float4(var[0], var[1], var[2], var[3]);
                *reinterpret_cast<float4*>(out + 2 * NTOT + idx + 4) = make_float4(var[4], var[5], var[6], var[7]);
                *reinterpret_cast<float4*>(out + 3 * NTOT + idx)     = make_float4(del[0], del[1], del[2], del[3]);
                *reinterpret_cast<float4*>(out + 3 * NTOT + idx + 4) = make_float4(del[4], del[5], del[6], del[7]);
                *reinterpret_cast<float4*>(out + 4 * NTOT + idx)     = make_float4(del[0], del[1], del[2], del[3]);
                *reinterpret_cast<float4*>(out + 4 * NTOT + idx + 4) = make_float4(del[4], del[5], del[6], del[7]);
            }
        }
    }
}

extern "C" void kernel_launch(void* const* d_in, const int* in_sizes, int n_in,
                              void* d_out, int out_size)
{
    const float* drive  = (const float*)d_in[0];   // [16,8,256,256] f32
    const float* Klocal = (const float*)d_in[1];   // [8,1,3,3] f32
    float* out = (float*)d_out;                    // 5 x [16,8,256,256] f32

    const int smem_bytes = 2 * BROWS * W * (int)sizeof(float);   // 196608
    cudaFuncSetAttribute(cml_fused_kernel,
                         cudaFuncAttributeMaxDynamicSharedMemorySize, smem_bytes);

    dim3 grid(HIMG / STRIP, 8, 16);    // 4 strips x 8 ch x 16 batch = 512 CTAs
    dim3 block(TXN, TYN);              // 512 threads
    cml_fused_kernel<<<grid, block, smem_bytes>>>(drive, Klocal, out);
}

// round 7
// speedup vs baseline: 1.0377x; 1.0377x over previous
#include <cuda_runtime.h>
#include <cstdint>

// ---------------------------------------------------------------------------
// CML2DWithStats, round 7: 4-CTA cluster per plane, DSMEM halo exchange.
//
//   g_{t+1} = clamp( conv3x3( m_t, K' ) + BETA*drive ),  m = g*(1-g)
//   K' = R*(1-BETA)*(EPS*K + (1-EPS)*delta_center)
//
// Cluster (4,1,1) spans one (batch,channel) plane; cluster rank = 64-row
// strip. Per-CTA smem: two 66-row mapped buffers (rows 0..63 own, slot 64 =
// top halo = up-neighbor row 63, slot 65 = bottom halo = down-neighbor row 0).
// Per step, warp ty==0 (ty==15) fetches the halo row via mapa +
// ld.shared::cluster and stores it into the local slot; that warp is the
// slot's only reader, so no intra-CTA barrier is needed. A cluster barrier
// (release/acquire) ends each step. Every thread computes exactly 2 row
// pairs; all computed rows are interior outputs (zero redundant work).
// ---------------------------------------------------------------------------

#define R_PARAM  3.9f
#define EPS_P    0.3f
#define BETA_P   0.15f
#define NSTEPS   15
#define CLAMP_LO 1e-4f
#define CLAMP_HI (1.0f - 1e-4f)

constexpr int W      = 256;
constexpr int RCTA   = 64;                 // rows per CTA
constexpr int BROWS  = 66;                 // 64 own + 2 halo slots
constexpr int TXN    = 32;
constexpr int TYN    = 16;
constexpr int NTHR   = TXN * TYN;          // 512
constexpr int NPLANE = W * 256;
constexpr long long NTOT = 16LL * 8 * NPLANE;
constexpr int BUF_ELEMS  = BROWS * W;          // 16896 floats
constexpr int SMEM_BYTES = 2 * BUF_ELEMS * 4;  // 135168 B

__device__ __forceinline__ float clampg(float v) {
    return fminf(fmaxf(v, CLAMP_LO), CLAMP_HI);
}

__device__ __forceinline__ uint32_t smem_u32(const void* p) {
    uint32_t a;
    asm("{ .reg .u64 t; cvta.to.shared.u64 t, %1; cvt.u32.u64 %0, t; }"
        : "=r"(a) : "l"(p));
    return a;
}

__device__ __forceinline__ float4 dsmem_ld4(uint32_t my_addr, uint32_t rank) {
    uint32_t ra; float4 v;
    asm volatile("mapa.shared::cluster.u32 %0, %1, %2;"
                 : "=r"(ra) : "r"(my_addr), "r"(rank));
    asm volatile("ld.shared::cluster.v4.f32 {%0, %1, %2, %3}, [%4];"
                 : "=f"(v.x), "=f"(v.y), "=f"(v.z), "=f"(v.w) : "r"(ra));
    return v;
}

#define CLUSTER_BAR()                                                       \
    do {                                                                    \
        asm volatile("barrier.cluster.arrive.aligned;" ::: "memory");       \
        asm volatile("barrier.cluster.wait.aligned;"   ::: "memory");       \
    } while (0)

__global__ void __launch_bounds__(NTHR, 1) __cluster_dims__(4, 1, 1)
cml_cluster_kernel(const float* __restrict__ drive,
                   const float* __restrict__ Klocal,
                   float* __restrict__ out)
{
    extern __shared__ float sm[];
    float* MB0 = sm;
    float* MB1 = sm + BUF_ELEMS;

    const int tx = threadIdx.x;
    const int ty = threadIdx.y;
    const int strip = blockIdx.x;          // == cluster rank, 0..3
    const int c     = blockIdx.y;
    const int b     = blockIdx.z;
    const int x4    = tx * 4;
    const int x0    = tx * 8;
    const int rbase = strip * RCTA;

    // Folded kernel K' = R*(1-BETA)*(EPS*K + (1-EPS)*delta)
    float kk[3][3];
    {
        const float* kc = Klocal + c * 9;
        #pragma unroll
        for (int j = 0; j < 3; ++j)
            #pragma unroll
            for (int i = 0; i < 3; ++i) {
                float v = EPS_P * kc[j * 3 + i];
                if (j == 1 && i == 1) v += (1.0f - EPS_P);
                kk[j][i] = R_PARAM * (1.0f - BETA_P) * v;
            }
    }

    const long long plane = (long long)(b * 8 + c) * NPLANE;
    const float* dpl = drive + plane;

    // Pair assignment: pA processed first (never boundary), pB second
    // (boundary pair 0 for ty==0, 31 for ty==15).
    const int pA = (ty == 0) ? 16 : ty;          // 1..16
    const int pB = (ty == 0) ? 0  : ty + 16;     // 0, 17..31
    const int A0 = 2 * pA - 1, A1 = 2 * pA, A2 = 2 * pA + 1, A3 = 2 * pA + 2;
    const int B0 = (pB == 0)  ? 64 : 2 * pB - 1;
    const int B1 = 2 * pB,     B2 = 2 * pB + 1;
    const int B3 = (pB == 31) ? 65 : 2 * pB + 2;
    const int irA = rbase + 2 * pA;
    const int irB = rbase + 2 * pB;

    // ---- init: MB0 rows 0..63 <- mapped(drive). No MB1 / halo-slot init
    //      needed: every read is produced earlier in program order. ----
    #pragma unroll
    for (int k = 0; k < 4; ++k) {
        int r = ty + TYN * k;                   // 0..63, always in-image
        const float* dr = dpl + (long long)(rbase + r) * W + x0;
        float4 dA = *reinterpret_cast<const float4*>(dr);
        float4 dB = *reinterpret_cast<const float4*>(dr + 4);
        float4 mA, mB;
        mA.x = fmaf(-dA.x, dA.x, dA.x);  mA.y = fmaf(-dA.y, dA.y, dA.y);
        mA.z = fmaf(-dA.z, dA.z, dA.z);  mA.w = fmaf(-dA.w, dA.w, dA.w);
        mB.x = fmaf(-dB.x, dB.x, dB.x);  mB.y = fmaf(-dB.y, dB.y, dB.y);
        mB.z = fmaf(-dB.z, dB.z, dB.z);  mB.w = fmaf(-dB.w, dB.w, dB.w);
        float* p0 = MB0 + r * W;
        *reinterpret_cast<float4*>(p0 + x4)       = mA;
        *reinterpret_cast<float4*>(p0 + 128 + x4) = mB;
    }
    CLUSTER_BAR();

    // stats: pair slots A and B. [rowInPair*8 + i]
    float sumA[16], ssqA[16], sumB[16], ssqB[16];
    #pragma unroll
    for (int i = 0; i < 16; ++i) {
        sumA[i] = 0.f; ssqA[i] = 0.f; sumB[i] = 0.f; ssqB[i] = 0.f;
    }

    // accumulate one loaded row (m0..m7,lm,rm live) into acc with kernel row cc
    #define ACCROW(acc, cc)                                                    \
        {                                                                      \
            float c0 = (cc)[0], c1 = (cc)[1], c2 = (cc)[2];                    \
            acc[0] = fmaf(c0, lm, fmaf(c1, m0, fmaf(c2, m1, acc[0])));         \
            acc[1] = fmaf(c0, m0, fmaf(c1, m1, fmaf(c2, m2, acc[1])));         \
            acc[2] = fmaf(c0, m1, fmaf(c1, m2, fmaf(c2, m3, acc[2])));         \
            acc[3] = fmaf(c0, m2, fmaf(c1, m3, fmaf(c2, m4, acc[3])));         \
            acc[4] = fmaf(c0, m3, fmaf(c1, m4, fmaf(c2, m5, acc[4])));         \
            acc[5] = fmaf(c0, m4, fmaf(c1, m5, fmaf(c2, m6, acc[5])));         \
            acc[6] = fmaf(c0, m5, fmaf(c1, m6, fmaf(c2, m7, acc[6])));         \
            acc[7] = fmaf(c0, m6, fmaf(c1, m7, fmaf(c2, rm, acc[7])));         \
        }

    // conv over explicit input rows R0..R3 (may be halo slots 64/65)
    #define PAIR_CONV(Min, R0, R1, R2, R3, acc0, acc1)                         \
        {                                                                      \
            const int rows_[4] = { (R0), (R1), (R2), (R3) };                   \
            _Pragma("unroll")                                                  \
            for (int jr = 0; jr < 4; ++jr) {                                   \
                const float* rp = (Min) + rows_[jr] * W;                       \
                float4 qa = *reinterpret_cast<const float4*>(rp + x4);         \
                float4 qb = *reinterpret_cast<const float4*>(rp + 128 + x4);   \
                float m0 = qa.x, m1 = qa.y, m2 = qa.z, m3 = qa.w;              \
                float m4 = qb.x, m5 = qb.y, m6 = qb.z, m7 = qb.w;              \
                float lm = __shfl_up_sync(0xffffffffu, m7, 1);                 \
                float rm = __shfl_down_sync(0xffffffffu, m0, 1);               \
                if (tx == 0)  lm = 0.f;                                        \
                if (tx == 31) rm = 0.f;                                        \
                if (jr < 3) ACCROW(acc0, kk[jr])                               \
                if (jr > 0) ACCROW(acc1, kk[jr - 1])                           \
            }                                                                  \
        }

    #define LOAD_DRIVE_RAW(ir, dv)                                             \
        {                                                                      \
            const float* dr = dpl + (long long)(ir) * W + x0;                  \
            float4 dA = *reinterpret_cast<const float4*>(dr);                  \
            float4 dB = *reinterpret_cast<const float4*>(dr + 4);              \
            dv[0] = dA.x;  dv[1] = dA.y;  dv[2] = dA.z;  dv[3] = dA.w;         \
            dv[4] = dB.x;  dv[5] = dB.y;  dv[6] = dB.z;  dv[7] = dB.w;         \
        }

    // per-step halo fetch into local slots (Min buffer); fetching warp is
    // the sole reader of its slot -> warp-internal smem dependency only.
    #define HALO_PROLOGUE(Min)                                                 \
        {                                                                      \
            if (ty == 0) {                                                     \
                float4 h0 = make_float4(0.f, 0.f, 0.f, 0.f), h1 = h0;          \
                if (strip > 0) {                                               \
                    uint32_t a = smem_u32((Min) + 63 * W + x4);                \
                    h0 = dsmem_ld4(a,       (uint32_t)(strip - 1));            \
                    h1 = dsmem_ld4(a + 512, (uint32_t)(strip - 1));            \
                }                                                              \
                *reinterpret_cast<float4*>((Min) + 64 * W + x4)       = h0;    \
                *reinterpret_cast<float4*>((Min) + 64 * W + 128 + x4) = h1;    \
            } else if (ty == 15) {                                             \
                float4 h0 = make_float4(0.f, 0.f, 0.f, 0.f), h1 = h0;          \
                if (strip < 3) {                                               \
                    uint32_t a = smem_u32((Min) + x4);                         \
                    h0 = dsmem_ld4(a,       (uint32_t)(strip + 1));            \
                    h1 = dsmem_ld4(a + 512, (uint32_t)(strip + 1));            \
                }                                                              \
                *reinterpret_cast<float4*>((Min) + 65 * W + x4)       = h0;    \
                *reinterpret_cast<float4*>((Min) + 65 * W + 128 + x4) = h1;    \
            }                                                                  \
        }

    // one pair for steps 0..13: conv -> g -> stats -> store mapped
    #define PAIR_STEP(Min, Mout, R0, R1, R2, R3, irr, orow, sumP, ssqP)        \
        {                                                                      \
            float dv0[8], dv1[8];                                              \
            LOAD_DRIVE_RAW((irr), dv0)                                         \
            LOAD_DRIVE_RAW((irr) + 1, dv1)                                     \
            float acc0[8] = {0.f,0.f,0.f,0.f,0.f,0.f,0.f,0.f};                 \
            float acc1[8] = {0.f,0.f,0.f,0.f,0.f,0.f,0.f,0.f};                 \
            PAIR_CONV(Min, R0, R1, R2, R3, acc0, acc1)                         \
            float g0[8], g1[8], mm0[8], mm1[8];                                \
            _Pragma("unroll")                                                  \
            for (int i = 0; i < 8; ++i) {                                      \
                g0[i]  = clampg(fmaf(BETA_P, dv0[i], acc0[i]));                \
                g1[i]  = clampg(fmaf(BETA_P, dv1[i], acc1[i]));                \
                mm0[i] = fmaf(-g0[i], g0[i], g0[i]);                           \
                mm1[i] = fmaf(-g1[i], g1[i], g1[i]);                           \
                sumP[i]     += g0[i];  ssqP[i]     = fmaf(g0[i], g0[i], ssqP[i]);      \
                sumP[i + 8] += g1[i];  ssqP[i + 8] = fmaf(g1[i], g1[i], ssqP[i + 8]);  \
            }                                                                  \
            float* op0 = (Mout) + (orow) * W;                                  \
            float* op1 = (Mout) + ((orow) + 1) * W;                            \
            *reinterpret_cast<float4*>(op0 + x4)       = make_float4(mm0[0], mm0[1], mm0[2], mm0[3]); \
            *reinterpret_cast<float4*>(op0 + 128 + x4) = make_float4(mm0[4], mm0[5], mm0[6], mm0[7]); \
            *reinterpret_cast<float4*>(op1 + x4)       = make_float4(mm1[0], mm1[1], mm1[2], mm1[3]); \
            *reinterpret_cast<float4*>(op1 + 128 + x4) = make_float4(mm1[4], mm1[5], mm1[6], mm1[7]); \
        }

    // ---- steps 0..13 ----
    #pragma unroll 1
    for (int t = 0; t < NSTEPS - 1; ++t) {
        float* Min  = (t & 1) ? MB1 : MB0;
        float* Mout = (t & 1) ? MB0 : MB1;

        HALO_PROLOGUE(Min)
        PAIR_STEP(Min, Mout, A0, A1, A2, A3, irA, 2 * pA, sumA, ssqA)
        PAIR_STEP(Min, Mout, B0, B1, B2, B3, irB, 2 * pB, sumB, ssqB)

        CLUSTER_BAR();
    }

    // ---- final step t=14 (reads MB0): compute pairs, write 5 outputs ----
    {
        float* Min = MB0;
        const float inv = 1.0f / (float)NSTEPS;

        HALO_PROLOGUE(Min)

        #pragma unroll
        for (int pp = 0; pp < 2; ++pp) {
            const int irr  = pp ? irB : irA;
            float* sumP = pp ? sumB : sumA;
            float* ssqP = pp ? ssqB : ssqA;

            float dv0[8], dv1[8];
            LOAD_DRIVE_RAW(irr, dv0)
            LOAD_DRIVE_RAW(irr + 1, dv1)

            float acc0[8] = {0.f,0.f,0.f,0.f,0.f,0.f,0.f,0.f};
            float acc1[8] = {0.f,0.f,0.f,0.f,0.f,0.f,0.f,0.f};
            if (pp == 0) { PAIR_CONV(Min, A0, A1, A2, A3, acc0, acc1) }
            else         { PAIR_CONV(Min, B0, B1, B2, B3, acc0, acc1) }

            #pragma unroll
            for (int half = 0; half < 2; ++half) {
                const float* acc = half ? acc1 : acc0;
                const float* dv  = half ? dv1  : dv0;
                const int off    = half * 8;
                long long idx = plane + (long long)(irr + half) * W + x0;

                float g[8], mean[8], var[8], del[8];
                #pragma unroll
                for (int i = 0; i < 8; ++i) {
                    g[i] = clampg(fmaf(BETA_P, dv[i], acc[i]));
                    float s  = sumP[off + i] + g[i];
                    float sq = fmaf(g[i], g[i], ssqP[off + i]);
                    mean[i] = s * inv;
                    var[i]  = fmaf(-mean[i], mean[i], sq * inv);
                    del[i]  = g[i] - dv[i];
                }
                *reinterpret_cast<float4*>(out + idx)                = make_float4(g[0], g[1], g[2], g[3]);
                *reinterpret_cast<float4*>(out + idx + 4)            = make_float4(g[4], g[5], g[6], g[7]);
                *reinterpret_cast<float4*>(out + NTOT + idx)         = make_float4(mean[0], mean[1], mean[2], mean[3]);
                *reinterpret_cast<float4*>(out + NTOT + idx + 4)     = make_float4(mean[4], mean[5], mean[6], mean[7]);
                *reinterpret_cast<float4*>(out + 2 * NTOT + idx)     = make_float4(var[0], var[1], var[2], var[3]);
                *reinterpret_cast<float4*>(out + 2 * NTOT + idx + 4) = make_float4(var[4], var[5], var[6], var[7]);
                *reinterpret_cast<float4*>(out + 3 * NTOT + idx)     = make_float4(del[0], del[1], del[2], del[3]);
                *reinterpret_cast<float4*>(out + 3 * NTOT + idx + 4) = make_float4(del[4], del[5], del[6], del[7]);
                *reinterpret_cast<float4*>(out + 4 * NTOT + idx)     = make_float4(del[0], del[1], del[2], del[3]);
                *reinterpret_cast<float4*>(out + 4 * NTOT + idx + 4) = make_float4(del[4], del[5], del[6], del[7]);
            }
        }
    }

    // no CTA may exit while a neighbor might still read our smem
    CLUSTER_BAR();
}

extern "C" void kernel_launch(void* const* d_in, const int* in_sizes, int n_in,
                              void* d_out, int out_size)
{
    const float* drive  = (const float*)d_in[0];   // [16,8,256,256] f32
    const float* Klocal = (const float*)d_in[1];   // [8,1,3,3] f32
    float* out = (float*)d_out;                    // 5 x [16,8,256,256] f32

    cudaFuncSetAttribute(cml_cluster_kernel,
                         cudaFuncAttributeMaxDynamicSharedMemorySize, SMEM_BYTES);

    dim3 grid(4, 8, 16);               // 4 strips (1 cluster/plane) x 8 ch x 16 b
    dim3 block(TXN, TYN);              // 512 threads
    cml_cluster_kernel<<<grid, block, SMEM_BYTES>>>(drive, Klocal, out);
}